// round 1
// baseline (speedup 1.0000x reference)
#include <cuda_runtime.h>

// EKF cell: B=262144 batches, N=8 state dim, M=4 measurement dim.
// One thread per batch element; all small-matrix math fully unrolled in registers.
//
// Inputs (metadata order):
//   0 measurement (B,4)  1 state (B,8)  2 state_cov (B,8,8)  3 F (B,8,8)
//   4 H (B,4,8)  5 process_noise (B,36)  6 measurement_noise (B,10)
// Output: concat of prediction (B,4), upd_state (B,8), upd_cov (B,8,8).

__global__ __launch_bounds__(256) void ekf_kernel(
    const float* __restrict__ g_meas,
    const float* __restrict__ g_state,
    const float* __restrict__ g_cov,
    const float* __restrict__ g_F,
    const float* __restrict__ g_H,
    const float* __restrict__ g_pn,
    const float* __restrict__ g_mn,
    float* __restrict__ o_pred,
    float* __restrict__ o_state,
    float* __restrict__ o_cov,
    int B)
{
    int b = blockIdx.x * blockDim.x + threadIdx.x;
    if (b >= B) return;

    // ---------------- loads (vectorized) ----------------
    float Fm[64], P[64];
    {
        const float4* f4 = reinterpret_cast<const float4*>(g_F) + (size_t)b * 16;
        const float4* p4 = reinterpret_cast<const float4*>(g_cov) + (size_t)b * 16;
        #pragma unroll
        for (int i = 0; i < 16; i++) {
            float4 v = f4[i];
            Fm[4*i+0] = v.x; Fm[4*i+1] = v.y; Fm[4*i+2] = v.z; Fm[4*i+3] = v.w;
        }
        #pragma unroll
        for (int i = 0; i < 16; i++) {
            float4 v = p4[i];
            P[4*i+0] = v.x; P[4*i+1] = v.y; P[4*i+2] = v.z; P[4*i+3] = v.w;
        }
    }
    float st[8];
    {
        const float4* s4 = reinterpret_cast<const float4*>(g_state) + (size_t)b * 2;
        float4 a = s4[0], c = s4[1];
        st[0]=a.x; st[1]=a.y; st[2]=a.z; st[3]=a.w;
        st[4]=c.x; st[5]=c.y; st[6]=c.z; st[7]=c.w;
    }

    // ---------------- predict ----------------
    // new_state = F @ state
    float ns[8];
    #pragma unroll
    for (int i = 0; i < 8; i++) {
        float a = 0.f;
        #pragma unroll
        for (int j = 0; j < 8; j++) a += Fm[i*8+j] * st[j];
        ns[i] = a;
    }

    // T = F @ P
    float T[64];
    #pragma unroll
    for (int i = 0; i < 8; i++) {
        #pragma unroll
        for (int k = 0; k < 8; k++) {
            float a = 0.f;
            #pragma unroll
            for (int j = 0; j < 8; j++) a += Fm[i*8+j] * P[j*8+k];
            T[i*8+k] = a;
        }
    }

    // Q = Lq Lq^T from 36 packed lower-tri elems; P' = T F^T + Q  (reuse P)
    float Lq[36];
    {
        const float2* q2 = reinterpret_cast<const float2*>(g_pn) + (size_t)b * 18;
        #pragma unroll
        for (int i = 0; i < 18; i++) { float2 v = q2[i]; Lq[2*i] = v.x; Lq[2*i+1] = v.y; }
    }
    #pragma unroll
    for (int i = 0; i < 8; i++) {
        #pragma unroll
        for (int l = 0; l < 8; l++) {
            float a = 0.f;
            // Q(i,l) = sum_{k<=min(i,l)} Lq[tri(i)+k]*Lq[tri(l)+k]
            #pragma unroll
            for (int k = 0; k < 8; k++) {
                if (k <= i && k <= l)
                    a += Lq[i*(i+1)/2 + k] * Lq[l*(l+1)/2 + k];
            }
            #pragma unroll
            for (int k = 0; k < 8; k++) a += T[i*8+k] * Fm[l*8+k];
            P[i*8+l] = a;   // P now holds new_state_cov
        }
    }

    // ---------------- update ----------------
    float Hm[32];
    {
        const float4* h4 = reinterpret_cast<const float4*>(g_H) + (size_t)b * 8;
        #pragma unroll
        for (int i = 0; i < 8; i++) {
            float4 v = h4[i];
            Hm[4*i+0] = v.x; Hm[4*i+1] = v.y; Hm[4*i+2] = v.z; Hm[4*i+3] = v.w;
        }
    }

    // prediction = H @ new_state ; res = meas - prediction
    float pred[4], res[4];
    {
        float4 mv = reinterpret_cast<const float4*>(g_meas)[b];
        float mea[4] = {mv.x, mv.y, mv.z, mv.w};
        #pragma unroll
        for (int i = 0; i < 4; i++) {
            float a = 0.f;
            #pragma unroll
            for (int j = 0; j < 8; j++) a += Hm[i*8+j] * ns[j];
            pred[i] = a;
            res[i] = mea[i] - a;
        }
    }

    // PHt = P' @ H^T   (8x4)
    float PHt[32];
    #pragma unroll
    for (int i = 0; i < 8; i++) {
        #pragma unroll
        for (int j = 0; j < 4; j++) {
            float a = 0.f;
            #pragma unroll
            for (int k = 0; k < 8; k++) a += P[i*8+k] * Hm[j*8+k];
            PHt[i*4+j] = a;
        }
    }

    // S = H @ PHt + R  (4x4, SPD)
    float A[16];
    {
        float Lr[10];
        const float2* r2 = reinterpret_cast<const float2*>(g_mn) + (size_t)b * 5;
        #pragma unroll
        for (int i = 0; i < 5; i++) { float2 v = r2[i]; Lr[2*i] = v.x; Lr[2*i+1] = v.y; }
        #pragma unroll
        for (int i = 0; i < 4; i++) {
            #pragma unroll
            for (int j = 0; j < 4; j++) {
                float a = 0.f;
                #pragma unroll
                for (int k = 0; k < 4; k++) {
                    if (k <= i && k <= j)
                        a += Lr[i*(i+1)/2 + k] * Lr[j*(j+1)/2 + k];
                }
                #pragma unroll
                for (int k = 0; k < 8; k++) a += Hm[i*8+k] * PHt[k*4+j];
                A[i*4+j] = a;
            }
        }
    }

    // Solve S X = [PHt^T | res]  (Gauss-Jordan, no pivot: S is SPD)
    // Rh rows r, cols 0..7 = PHt^T (i.e. PHt[c][r]), col 8 = res[r]
    float Rh[36];
    #pragma unroll
    for (int r = 0; r < 4; r++) {
        #pragma unroll
        for (int c = 0; c < 8; c++) Rh[r*9+c] = PHt[c*4+r];
        Rh[r*9+8] = res[r];
    }
    #pragma unroll
    for (int c = 0; c < 4; c++) {
        float inv = 1.0f / A[c*4+c];
        #pragma unroll
        for (int j = 0; j < 4; j++) A[c*4+j] *= inv;
        #pragma unroll
        for (int j = 0; j < 9; j++) Rh[c*9+j] *= inv;
        #pragma unroll
        for (int r = 0; r < 4; r++) {
            if (r == c) continue;
            float f = A[r*4+c];
            #pragma unroll
            for (int j = 0; j < 4; j++) A[r*4+j] -= f * A[c*4+j];
            #pragma unroll
            for (int j = 0; j < 9; j++) Rh[r*9+j] -= f * Rh[c*9+j];
        }
    }

    // upd_state = ns + PHt @ z   where z = S^{-1} res
    float us[8];
    {
        float z[4];
        #pragma unroll
        for (int r = 0; r < 4; r++) z[r] = Rh[r*9+8];
        #pragma unroll
        for (int i = 0; i < 8; i++) {
            float a = ns[i];
            #pragma unroll
            for (int j = 0; j < 4; j++) a += PHt[i*4+j] * z[j];
            us[i] = a;
        }
    }

    // K = PHt S^{-1}  -> K[i][j] = Rh[j][i]
    float K[32];
    #pragma unroll
    for (int i = 0; i < 8; i++)
        #pragma unroll
        for (int j = 0; j < 4; j++)
            K[i*4+j] = Rh[j*9+i];

    // ---------------- stores ----------------
    reinterpret_cast<float4*>(o_pred)[b] = make_float4(pred[0], pred[1], pred[2], pred[3]);
    {
        float4* s4 = reinterpret_cast<float4*>(o_state) + (size_t)b * 2;
        s4[0] = make_float4(us[0], us[1], us[2], us[3]);
        s4[1] = make_float4(us[4], us[5], us[6], us[7]);
    }

    // upd_cov = (I - K H) P'  computed row-wise, fused with store
    float4* c4 = reinterpret_cast<float4*>(o_cov) + (size_t)b * 16;
    #pragma unroll
    for (int i = 0; i < 8; i++) {
        float kh[8];
        #pragma unroll
        for (int l = 0; l < 8; l++) {
            float a = 0.f;
            #pragma unroll
            for (int j = 0; j < 4; j++) a += K[i*4+j] * Hm[j*8+l];
            kh[l] = a;
        }
        float row[8];
        #pragma unroll
        for (int l = 0; l < 8; l++) {
            float a = P[i*8+l];
            #pragma unroll
            for (int k = 0; k < 8; k++) a -= kh[k] * P[k*8+l];
            row[l] = a;
        }
        c4[i*2+0] = make_float4(row[0], row[1], row[2], row[3]);
        c4[i*2+1] = make_float4(row[4], row[5], row[6], row[7]);
    }
}

extern "C" void kernel_launch(void* const* d_in, const int* in_sizes, int n_in,
                              void* d_out, int out_size)
{
    const float* g_meas = (const float*)d_in[0];
    const float* g_state = (const float*)d_in[1];
    const float* g_cov  = (const float*)d_in[2];
    const float* g_F    = (const float*)d_in[3];
    const float* g_H    = (const float*)d_in[4];
    const float* g_pn   = (const float*)d_in[5];
    const float* g_mn   = (const float*)d_in[6];

    int B = in_sizes[0] / 4;   // measurement is (B, 4)

    float* o_pred  = (float*)d_out;            // (B,4)
    float* o_state = o_pred + (size_t)B * 4;   // (B,8)
    float* o_cov   = o_state + (size_t)B * 8;  // (B,8,8)

    int threads = 256;
    int blocks = (B + threads - 1) / threads;
    ekf_kernel<<<blocks, threads>>>(g_meas, g_state, g_cov, g_F, g_H, g_pn, g_mn,
                                    o_pred, o_state, o_cov, B);
}

// round 2
// speedup vs baseline: 1.2372x; 1.2372x over previous
#include <cuda_runtime.h>

// EKF cell: B=262144, N=8, M=4. One thread per batch, symmetric-matrix
// register compression + launch-bounds cap for occupancy.
//
// Symmetry used:
//   P (input state_cov) symmetric -> 36 tri regs
//   P' = F P F^T + Q symmetric    -> 36 tri regs, Q added after F,G die
//   upd_cov = P' - PHt S^-1 PHt^T symmetric -> 36 computed, mirrored at store
//   (H P' = PHt^T, so H is dead after S is formed)

__device__ __forceinline__ float psym(const float* t, int i, int j) {
    return (i >= j) ? t[i*(i+1)/2 + j] : t[j*(j+1)/2 + i];
}

__global__ __launch_bounds__(128, 3) void ekf_kernel(
    const float* __restrict__ g_meas,
    const float* __restrict__ g_state,
    const float* __restrict__ g_cov,
    const float* __restrict__ g_F,
    const float* __restrict__ g_H,
    const float* __restrict__ g_pn,
    const float* __restrict__ g_mn,
    float* __restrict__ o_pred,
    float* __restrict__ o_state,
    float* __restrict__ o_cov,
    int B)
{
    int b = blockIdx.x * blockDim.x + threadIdx.x;
    if (b >= B) return;

    // ---- load F (full 64) and P (lower-tri 36 of symmetric input) ----
    float Fm[64];
    {
        const float4* f4 = reinterpret_cast<const float4*>(g_F) + (size_t)b * 16;
        #pragma unroll
        for (int v = 0; v < 16; v++) {
            float4 x = f4[v];
            Fm[4*v+0] = x.x; Fm[4*v+1] = x.y; Fm[4*v+2] = x.z; Fm[4*v+3] = x.w;
        }
    }
    float Pt[36];
    {
        const float4* p4 = reinterpret_cast<const float4*>(g_cov) + (size_t)b * 16;
        #pragma unroll
        for (int v = 0; v < 16; v++) {
            float4 x = p4[v];
            float vals[4] = {x.x, x.y, x.z, x.w};
            #pragma unroll
            for (int c = 0; c < 4; c++) {
                int e = 4*v + c, i = e >> 3, j = e & 7;
                if (i >= j) Pt[i*(i+1)/2 + j] = vals[c];
            }
        }
    }

    // ---- new_state = F @ state ----
    float ns[8];
    {
        const float4* s4 = reinterpret_cast<const float4*>(g_state) + (size_t)b * 2;
        float4 a = s4[0], c = s4[1];
        float st[8] = {a.x, a.y, a.z, a.w, c.x, c.y, c.z, c.w};
        #pragma unroll
        for (int i = 0; i < 8; i++) {
            float acc = 0.f;
            #pragma unroll
            for (int j = 0; j < 8; j++) acc += Fm[i*8+j] * st[j];
            ns[i] = acc;
        }
    }

    // ---- G = P @ F^T  (8x8; uses symmetric P) ----
    float G[64];
    #pragma unroll
    for (int j = 0; j < 8; j++) {
        #pragma unroll
        for (int l = 0; l < 8; l++) {
            float a = 0.f;
            #pragma unroll
            for (int k = 0; k < 8; k++) a += psym(Pt, j, k) * Fm[l*8+k];
            G[j*8+l] = a;
        }
    }

    // ---- P' = F @ G  (lower tri only; overwrite Pt) ----
    float Pp[36];
    #pragma unroll
    for (int i = 0; i < 8; i++) {
        #pragma unroll
        for (int l = 0; l <= i; l++) {
            float a = 0.f;
            #pragma unroll
            for (int j = 0; j < 8; j++) a += Fm[i*8+j] * G[j*8+l];
            Pp[i*(i+1)/2 + l] = a;
        }
    }
    // F, G, Pt dead here.

    // ---- P' += Q = Lq Lq^T  (tri) ----
    {
        float Lq[36];
        const float2* q2 = reinterpret_cast<const float2*>(g_pn) + (size_t)b * 18;
        #pragma unroll
        for (int i = 0; i < 18; i++) { float2 v = q2[i]; Lq[2*i] = v.x; Lq[2*i+1] = v.y; }
        #pragma unroll
        for (int i = 0; i < 8; i++) {
            #pragma unroll
            for (int l = 0; l <= i; l++) {
                float a = Pp[i*(i+1)/2 + l];
                #pragma unroll
                for (int k = 0; k <= l; k++)
                    a += Lq[i*(i+1)/2 + k] * Lq[l*(l+1)/2 + k];
                Pp[i*(i+1)/2 + l] = a;
            }
        }
    }

    // ---- load H, measurement; prediction & residual ----
    float Hm[32];
    {
        const float4* h4 = reinterpret_cast<const float4*>(g_H) + (size_t)b * 8;
        #pragma unroll
        for (int v = 0; v < 8; v++) {
            float4 x = h4[v];
            Hm[4*v+0] = x.x; Hm[4*v+1] = x.y; Hm[4*v+2] = x.z; Hm[4*v+3] = x.w;
        }
    }
    float pred[4], res[4];
    {
        float4 mv = reinterpret_cast<const float4*>(g_meas)[b];
        float mea[4] = {mv.x, mv.y, mv.z, mv.w};
        #pragma unroll
        for (int i = 0; i < 4; i++) {
            float a = 0.f;
            #pragma unroll
            for (int j = 0; j < 8; j++) a += Hm[i*8+j] * ns[j];
            pred[i] = a;
            res[i] = mea[i] - a;
        }
    }

    // ---- PHt = P' @ H^T  (8x4) ----
    float PHt[32];
    #pragma unroll
    for (int i = 0; i < 8; i++) {
        #pragma unroll
        for (int j = 0; j < 4; j++) {
            float a = 0.f;
            #pragma unroll
            for (int k = 0; k < 8; k++) a += psym(Pp, i, k) * Hm[j*8+k];
            PHt[i*4+j] = a;
        }
    }

    // ---- S = H @ PHt + R  (4x4 SPD) ----
    float A[16];
    {
        float Lr[10];
        const float2* r2 = reinterpret_cast<const float2*>(g_mn) + (size_t)b * 5;
        #pragma unroll
        for (int i = 0; i < 5; i++) { float2 v = r2[i]; Lr[2*i] = v.x; Lr[2*i+1] = v.y; }
        #pragma unroll
        for (int i = 0; i < 4; i++) {
            #pragma unroll
            for (int j = 0; j < 4; j++) {
                float a = 0.f;
                #pragma unroll
                for (int k = 0; k <= ((i < j) ? i : j); k++)
                    a += Lr[i*(i+1)/2 + k] * Lr[j*(j+1)/2 + k];
                #pragma unroll
                for (int k = 0; k < 8; k++) a += Hm[i*8+k] * PHt[k*4+j];
                A[i*4+j] = a;
            }
        }
    }
    // H dead here (not needed in epilogue thanks to symmetry identity).

    // ---- Solve S X = [PHt^T | res]  (Gauss-Jordan, pivot-free: S SPD) ----
    float Rh[36];
    #pragma unroll
    for (int r = 0; r < 4; r++) {
        #pragma unroll
        for (int c = 0; c < 8; c++) Rh[r*9+c] = PHt[c*4+r];
        Rh[r*9+8] = res[r];
    }
    #pragma unroll
    for (int c = 0; c < 4; c++) {
        float inv = 1.0f / A[c*4+c];
        #pragma unroll
        for (int j = 0; j < 4; j++) A[c*4+j] *= inv;
        #pragma unroll
        for (int j = 0; j < 9; j++) Rh[c*9+j] *= inv;
        #pragma unroll
        for (int r = 0; r < 4; r++) {
            if (r == c) continue;
            float f = A[r*4+c];
            #pragma unroll
            for (int j = 0; j < 4; j++) A[r*4+j] -= f * A[c*4+j];
            #pragma unroll
            for (int j = 0; j < 9; j++) Rh[r*9+j] -= f * Rh[c*9+j];
        }
    }
    // X = Rh[:,0:8] = S^-1 PHt^T ; z = Rh[:,8] = S^-1 res

    // ---- upd_state = ns + PHt @ z ----
    float us[8];
    #pragma unroll
    for (int i = 0; i < 8; i++) {
        float a = ns[i];
        #pragma unroll
        for (int j = 0; j < 4; j++) a += PHt[i*4+j] * Rh[j*9+8];
        us[i] = a;
    }

    // ---- stores ----
    reinterpret_cast<float4*>(o_pred)[b] = make_float4(pred[0], pred[1], pred[2], pred[3]);
    {
        float4* s4 = reinterpret_cast<float4*>(o_state) + (size_t)b * 2;
        s4[0] = make_float4(us[0], us[1], us[2], us[3]);
        s4[1] = make_float4(us[4], us[5], us[6], us[7]);
    }

    // ---- upd_cov = P' - PHt X  (symmetric; compute tri, mirror) ----
    float UC[36];
    #pragma unroll
    for (int i = 0; i < 8; i++) {
        #pragma unroll
        for (int l = 0; l <= i; l++) {
            float a = Pp[i*(i+1)/2 + l];
            #pragma unroll
            for (int j = 0; j < 4; j++) a -= PHt[i*4+j] * Rh[j*9+l];
            UC[i*(i+1)/2 + l] = a;
        }
    }
    float4* c4 = reinterpret_cast<float4*>(o_cov) + (size_t)b * 16;
    #pragma unroll
    for (int i = 0; i < 8; i++) {
        c4[i*2+0] = make_float4(psym(UC,i,0), psym(UC,i,1), psym(UC,i,2), psym(UC,i,3));
        c4[i*2+1] = make_float4(psym(UC,i,4), psym(UC,i,5), psym(UC,i,6), psym(UC,i,7));
    }
}

extern "C" void kernel_launch(void* const* d_in, const int* in_sizes, int n_in,
                              void* d_out, int out_size)
{
    const float* g_meas = (const float*)d_in[0];
    const float* g_state = (const float*)d_in[1];
    const float* g_cov  = (const float*)d_in[2];
    const float* g_F    = (const float*)d_in[3];
    const float* g_H    = (const float*)d_in[4];
    const float* g_pn   = (const float*)d_in[5];
    const float* g_mn   = (const float*)d_in[6];

    int B = in_sizes[0] / 4;   // measurement is (B, 4)

    float* o_pred  = (float*)d_out;
    float* o_state = o_pred + (size_t)B * 4;
    float* o_cov   = o_state + (size_t)B * 8;

    int threads = 128;
    int blocks = (B + threads - 1) / threads;
    ekf_kernel<<<blocks, threads>>>(g_meas, g_state, g_cov, g_F, g_H, g_pn, g_mn,
                                    o_pred, o_state, o_cov, B);
}